// round 16
// baseline (speedup 1.0000x reference)
#include <cuda_runtime.h>
#include <cuda_fp16.h>
#include <cstdint>

#define DIM    256
#define HW     1024
#define NTOT   32768
#define KCODES 1024
#define MT     128
#define GBLOCKS (NTOT / MT)              // 256
#define ZQ_ELEMS  ((size_t)NTOT * DIM)
#define CODES_OFF ZQ_ELEMS
#define LOSS_OFF  (ZQ_ELEMS + (size_t)NTOT)

// gemm smem layout (4B words)
#define OFF_A   0                         // 128 rows * 132 words (A hi only)
#define OFF_B   16896                     // 2 stages x 128*68
#define BSTG_W  8704
#define OFF_C   34304                     // 128*68 score tile (reused as RED post-loop)
#define OFF_ES  43008                     // 1024
#define OFF_ZNP 44032                     // 256
#define SMEM_WORDS 44288
#define SMEM_BYTES (SMEM_WORDS * 4)       // 177152

// empirically validated window constants
#define C1W 5.2e-4f
#define C3W 0.06f

__device__ __half g_eh[(size_t)KCODES * DIM];
__device__ float  g_en2[KCODES];
__device__ int    g_en2imax;
__device__ int    g_codes[NTOT];
__device__ float  g_partials[GBLOCKS];
__device__ int    g_fcnt;                 // candidate-refine list (<=3 extra)
__device__ int    g_flist[NTOT];
__device__ int4   g_cand[NTOT];
__device__ int    g_fcnt2;                // overflow list (rare)
__device__ int    g_flist2[NTOT];

__device__ __forceinline__ uint32_t smem_u32(const void* p) {
    uint32_t a;
    asm("{ .reg .u64 t; cvta.to.shared.u64 t, %1; cvt.u32.u64 %0, t; }" : "=r"(a) : "l"(p));
    return a;
}
__device__ __forceinline__ uint32_t pack2h(float x0, float x1) {
    uint32_t h2;
    asm("cvt.rn.f16x2.f32 %0, %1, %2;" : "=r"(h2) : "f"(x1), "f"(x0));
    return h2;
}

#define MMA16(c, a, b0, b1)                                                   \
    asm volatile("mma.sync.aligned.m16n8k16.row.col.f32.f16.f16.f32 "         \
        "{%0,%1,%2,%3}, {%4,%5,%6,%7}, {%8,%9}, {%0,%1,%2,%3};"               \
        : "+f"((c)[0]), "+f"((c)[1]), "+f"((c)[2]), "+f"((c)[3])              \
        : "r"((a)[0]), "r"((a)[1]), "r"((a)[2]), "r"((a)[3]),                 \
          "r"(b0), "r"(b1))
#define LDSM4(r0, r1, r2, r3, addr)                                           \
    asm volatile("ldmatrix.sync.aligned.m8n8.x4.shared.b16 {%0,%1,%2,%3}, [%4];" \
        : "=r"(r0), "=r"(r1), "=r"(r2), "=r"(r3) : "r"(addr))
#define CPA16(dst, src) \
    asm volatile("cp.async.cg.shared.global [%0], [%1], 16;" :: "r"(dst), "l"(src) : "memory")
#define CP_COMMIT() asm volatile("cp.async.commit_group;" ::: "memory")
#define CP_WAIT1()  asm volatile("cp.async.wait_group 1;" ::: "memory")

// ascending-k insert into top-4 (strict < => first-min)
#define INS4(s, k)                                                             \
    if ((s) < M4) {                                                            \
        if ((s) < M1)      { M4=M3; M3=M2; I3=I2; M2=M1; I2=I1; M1=(s); I1=(k); } \
        else if ((s) < M2) { M4=M3; M3=M2; I3=I2; M2=(s); I2=(k); }            \
        else if ((s) < M3) { M4=M3; M3=(s); I3=(k); }                          \
        else               { M4=(s); }                                         \
    }
// merge one (v,ix) into sorted-4 with index tie-break
#define MRG4(v, ix)                                                            \
    if ((v) < M1 || ((v) == M1 && (ix) < I1)) { M4=M3; M3=M2; I3=I2; M2=M1; I2=I1; M1=(v); I1=(ix); } \
    else if ((v) < M2 || ((v) == M2 && (ix) < I2)) { M4=M3; M3=M2; I3=I2; M2=(v); I2=(ix); } \
    else if ((v) < M3 || ((v) == M3 && (ix) < I3)) { M4=M3; M3=(v); I3=(ix); } \
    else if ((v) < M4) { M4=(v); }

// ---------------- prepass: emb hi-split + ||e||^2 + counters ----------------
__global__ void vq_prep_e(const float* __restrict__ emb) {
    if (blockIdx.x == 0 && threadIdx.x == 0) { g_fcnt = 0; g_fcnt2 = 0; }
    int gw = (blockIdx.x * blockDim.x + threadIdx.x) >> 5, lane = threadIdx.x & 31;
    if (gw >= KCODES) return;
    const float* row = emb + (size_t)gw * DIM;
    const int d0 = lane * 8;
    float4 v0 = *reinterpret_cast<const float4*>(row + d0);
    float4 v1 = *reinterpret_cast<const float4*>(row + d0 + 4);
    uint4 h;
    h.x = pack2h(v0.x, v0.y);
    h.y = pack2h(v0.z, v0.w);
    h.z = pack2h(v1.x, v1.y);
    h.w = pack2h(v1.z, v1.w);
    *reinterpret_cast<uint4*>(g_eh + (size_t)gw * DIM + d0) = h;
    float s = v0.x*v0.x + v0.y*v0.y + v0.z*v0.z + v0.w*v0.w
            + v1.x*v1.x + v1.y*v1.y + v1.z*v1.z + v1.w*v1.w;
    #pragma unroll
    for (int o = 16; o; o >>= 1) s += __shfl_xor_sync(0xFFFFFFFFu, s, o);
    if (lane == 0) {
        g_en2[gw] = s;
        atomicMax(&g_en2imax, __float_as_int(s));
    }
}

// B chunk loader
__device__ __forceinline__ void b_cpa(int c, uint32_t dstB, int tid) {
    const int nc = c >> 1, kh = c & 1;
    const __half* src = g_eh + (size_t)(nc * 128) * DIM + kh * 128;
    #pragma unroll
    for (int q = 0; q < 8; q++) {
        int idx = tid + q * 256;
        int n = idx >> 4, j = idx & 15;
        CPA16(dstB + n * 272 + j * 16, src + (size_t)n * DIM + j * 8);
    }
}

// ---------------- fused gemm + in-smem top-4 scan + decision ----------------
__global__ __launch_bounds__(256, 1)
void vq_gemm(const float* __restrict__ z, float* __restrict__ out) {
    extern __shared__ __align__(16) uint32_t sw[];
    float* es = reinterpret_cast<float*>(sw + OFF_ES);
    const int tid = threadIdx.x, wid = tid >> 5, lane = tid & 31;
    const int wm = wid & 3, wn = wid >> 2;
    const int tig = lane & 3, grp = lane >> 2;
    const int n0 = blockIdx.x * MT;
    const int b = n0 >> 10, hw0 = n0 & (HW - 1);

    const uint32_t sbase = smem_u32(sw);
    const uint32_t bBase = sbase + OFF_B * 4;

    b_cpa(0, bBase, tid);
    CP_COMMIT();
    b_cpa(1, bBase + BSTG_W * 4, tid);
    CP_COMMIT();

    // A: direct load from z, hi-split into smem; row-norm partial for free
    {
        const int m = tid & 127, khalf = tid >> 7;
        const float* zc = z + (size_t)b * DIM * HW + hw0 + m;
        uint32_t* ah = sw + OFF_A + m * 132 + khalf * 64;
        float zn = 0.f;
        #pragma unroll 8
        for (int j = 0; j < 64; j++) {
            const int k = khalf * 128 + 2 * j;
            float x0 = __ldg(zc + (size_t)k * HW);
            float x1 = __ldg(zc + (size_t)(k + 1) * HW);
            zn = fmaf(x0, x0, fmaf(x1, x1, zn));
            ah[j] = pack2h(x0, x1);
        }
        reinterpret_cast<float*>(sw + OFF_ZNP)[tid] = zn;
    }
    for (int i = tid; i < KCODES; i += 256) es[i] = g_en2[i];

    const int mrow = wm * 32 + ((lane >> 3) & 1) * 8 + (lane & 7);
    const uint32_t aAddr = sbase + mrow * 528 + (lane >> 4) * 16;
    const int nrow = wn * 64 + ((lane >> 4) << 3) + (lane & 7);
    const uint32_t bAddr0 = bBase + nrow * 272 + ((lane >> 3) & 1) * 16;

    // per-thread running top-4 for its owned row half
    const int srow = tid & 127, shf = tid >> 7;
    float M1 = 3.4e38f, M2 = 3.4e38f, M3 = 3.4e38f, M4 = 3.4e38f;
    int I1 = 0, I2 = 0, I3 = 0;
    __half Th = __ushort_as_half((unsigned short)0x7C00u);   // +inf

    float acc[2][8][4];

    #pragma unroll 1
    for (int c = 0; c < 16; c++) {
        const int nc = c >> 1, st = c & 1;
        CP_WAIT1();
        __syncthreads();

        if ((c & 1) == 0) {
            #pragma unroll
            for (int mt = 0; mt < 2; mt++)
                #pragma unroll
                for (int nt = 0; nt < 8; nt++)
                    #pragma unroll
                    for (int q = 0; q < 4; q++) acc[mt][nt][q] = 0.f;
        }

        #pragma unroll
        for (int kk = 0; kk < 8; kk++) {
            const uint32_t ak = (c & 1) * 256 + kk * 32;
            uint32_t ah[2][4];
            #pragma unroll
            for (int mt = 0; mt < 2; mt++)
                LDSM4(ah[mt][0], ah[mt][1], ah[mt][2], ah[mt][3],
                      aAddr + mt * (16 * 528) + ak);
            const uint32_t bk = st * (BSTG_W * 4) + kk * 32;
            #pragma unroll
            for (int ntp = 0; ntp < 4; ntp++) {
                uint32_t bh[4];
                LDSM4(bh[0], bh[1], bh[2], bh[3], bAddr0 + bk + ntp * (16 * 272));
                #pragma unroll
                for (int hf = 0; hf < 2; hf++) {
                    const int nt = ntp * 2 + hf;
                    #pragma unroll
                    for (int mt = 0; mt < 2; mt++)
                        MMA16(acc[mt][nt], ah[mt], bh[hf * 2], bh[hf * 2 + 1]);
                }
            }
        }
        __syncthreads();

        if (c + 2 < 16) { b_cpa(c + 2, bBase + st * (BSTG_W * 4), tid); CP_COMMIT(); }

        if (c & 1) {
            // stage scores into C smem tile
            #pragma unroll
            for (int mt = 0; mt < 2; mt++) {
                const int rbase = wm * 32 + mt * 16 + grp;
                #pragma unroll
                for (int nt = 0; nt < 8; nt++) {
                    const int col = wn * 64 + nt * 8 + tig * 2;
                    const float e0 = es[nc * 128 + col], e1 = es[nc * 128 + col + 1];
                    const int cw = wn * 32 + nt * 4 + tig;
                    __half2 p01 = __floats2half2_rn(fmaf(-2.f, acc[mt][nt][0], e0),
                                                    fmaf(-2.f, acc[mt][nt][1], e1));
                    __half2 p23 = __floats2half2_rn(fmaf(-2.f, acc[mt][nt][2], e0),
                                                    fmaf(-2.f, acc[mt][nt][3], e1));
                    sw[OFF_C + rbase * 68 + cw]       = *reinterpret_cast<uint32_t*>(&p01);
                    sw[OFF_C + (rbase + 8) * 68 + cw] = *reinterpret_cast<uint32_t*>(&p23);
                }
            }
            __syncthreads();
            // pack-pruned top-4 scan of owned row half (ascending k)
            const uint32_t* crow = sw + OFF_C + srow * 68 + shf * 32;
            const int kb0 = nc * 128 + shf * 64;
            #pragma unroll
            for (int p = 0; p < 8; p++) {
                uint4 v = *reinterpret_cast<const uint4*>(crow + p * 4);
                const __half2* hh = reinterpret_cast<const __half2*>(&v);
                __half2 mm = __hmin2(__hmin2(hh[0], hh[1]), __hmin2(hh[2], hh[3]));
                __half pm = __hmin(__low2half(mm), __high2half(mm));
                if (__hlt(pm, Th)) {
                    const int k0 = kb0 + p * 8;
                    #pragma unroll
                    for (int t = 0; t < 4; t++) {
                        float2 s2 = __half22float2(hh[t]);
                        const int kk2 = k0 + t * 2;
                        INS4(s2.x, kk2)
                        INS4(s2.y, kk2 + 1)
                    }
                    Th = __float2half_ru(M4);
                }
            }
        }
    }

    // merge the two half-threads per row, decide
    __syncthreads();
    float* RED = reinterpret_cast<float*>(sw + OFF_C);
    int*   REDi = reinterpret_cast<int*>(sw + OFF_C);
    RED[tid * 7] = M1; REDi[tid * 7 + 1] = I1;
    RED[tid * 7 + 2] = M2; REDi[tid * 7 + 3] = I2;
    RED[tid * 7 + 4] = M3; REDi[tid * 7 + 5] = I3;
    RED[tid * 7 + 6] = M4;
    __syncthreads();

    if (tid < 128) {
        const int e1 = (128 + tid) * 7;
        {
            float v1 = RED[e1];     int x1 = REDi[e1 + 1];
            float v2 = RED[e1 + 2]; int x2 = REDi[e1 + 3];
            float v3 = RED[e1 + 4]; int x3 = REDi[e1 + 5];
            float v4 = RED[e1 + 6];
            MRG4(v1, x1)
            MRG4(v2, x2)
            MRG4(v3, x3)
            M4 = fminf(M4, v4);
        }

        const int r = n0 + tid;
        g_codes[r] = I1;
        out[CODES_OFF + r] = (float)I1;

        const float* znp = reinterpret_cast<const float*>(sw + OFF_ZNP);
        const float czn = C1W * (znp[tid] + znp[tid + 128]);
        const float w1 = fmaf(C1W, __ldg(g_en2 + I1), C3W) + czn;
        const float wmax = fmaf(C1W, __int_as_float(g_en2imax), C3W) + czn;
        const float U = M1 + w1;
        if (M4 - wmax <= U) {
            int slot = atomicAdd(&g_fcnt2, 1);
            g_flist2[slot] = r;
        } else {
            int ks[3]; int nOth = 0;
            if (M2 - (fmaf(C1W, __ldg(g_en2 + I2), C3W) + czn) <= U) ks[nOth++] = I2;
            if (M3 - (fmaf(C1W, __ldg(g_en2 + I3), C3W) + czn) <= U) ks[nOth++] = I3;
            if (nOth > 0) {
                int slot = atomicAdd(&g_fcnt, 1);
                g_flist[slot] = r;
                g_cand[r] = make_int4(nOth + 1, I1, ks[0], (nOth > 1) ? ks[1] : -1);
            }
        }
    }
}

// ---------------- refine A: warp per row, <=3 exact fp32 dots ----------------
__global__ __launch_bounds__(256, 1)
void vq_refineA(const float* __restrict__ z, const float* __restrict__ emb,
                float* __restrict__ out) {
    const int tid = threadIdx.x, lane = tid & 31, wq = tid >> 5;
    const int gw = blockIdx.x * 8 + wq;
    const int nwarp = gridDim.x * 8;
    const int cnt = g_fcnt;
    for (int i = gw; i < cnt; i += nwarp) {
        const int r = g_flist[i];
        const int4 cd = g_cand[r];
        const int bb = r >> 10, hw = r & 1023;
        const float* zr = z + (size_t)bb * DIM * HW + hw;
        float zo[8];
        #pragma unroll
        for (int t = 0; t < 8; t++) zo[t] = __ldg(zr + (size_t)(lane * 8 + t) * HW);
        float bv = 3.4e38f; int bk = 0x7FFFFFFF;
        const int ks[3] = {cd.y, cd.z, cd.w};
        for (int c = 0; c < cd.x; c++) {
            const int k = ks[c];
            const float4* ep = reinterpret_cast<const float4*>(emb + (size_t)k * DIM + lane * 8);
            float4 ea = __ldg(ep), eb = __ldg(ep + 1);
            float d = zo[0]*ea.x + zo[1]*ea.y + zo[2]*ea.z + zo[3]*ea.w
                    + zo[4]*eb.x + zo[5]*eb.y + zo[6]*eb.z + zo[7]*eb.w;
            #pragma unroll
            for (int o = 16; o; o >>= 1) d += __shfl_xor_sync(0xFFFFFFFFu, d, o);
            float s = __ldg(g_en2 + k) - 2.f * d;
            if (s < bv || (s == bv && k < bk)) { bv = s; bk = k; }
        }
        if (lane == 0) { g_codes[r] = bk; out[CODES_OFF + r] = (float)bk; }
    }
}

// ---------------- refine B: block per row, full fp32 scan (rare) ----------------
__global__ __launch_bounds__(256, 1)
void vq_refineB(const float* __restrict__ z, const float* __restrict__ emb,
                float* __restrict__ out) {
    __shared__ float zs[DIM];
    __shared__ float rv[8];
    __shared__ int   rix[8];
    const int tid = threadIdx.x, lane = tid & 31, wid = tid >> 5;
    const int cnt = g_fcnt2;
    for (int i = blockIdx.x; i < cnt; i += gridDim.x) {
        const int r = g_flist2[i];
        const int bb = r >> 10, hw = r & 1023;
        zs[tid] = __ldg(z + (size_t)bb * DIM * HW + (size_t)tid * HW + hw);
        __syncthreads();
        float bv = 3.4e38f; int bk = 0x7FFFFFFF;
        #pragma unroll
        for (int j = 0; j < 4; j++) {
            const int k = tid * 4 + j;
            const float4* ep = reinterpret_cast<const float4*>(emb + (size_t)k * DIM);
            float d = 0.f;
            #pragma unroll 8
            for (int q = 0; q < 64; q++) {
                float4 e = __ldg(ep + q);
                d += zs[4*q]*e.x + zs[4*q+1]*e.y + zs[4*q+2]*e.z + zs[4*q+3]*e.w;
            }
            float s = __ldg(g_en2 + k) - 2.f * d;
            if (s < bv || (s == bv && k < bk)) { bv = s; bk = k; }
        }
        #pragma unroll
        for (int o = 16; o; o >>= 1) {
            float ov = __shfl_xor_sync(0xFFFFFFFFu, bv, o);
            int   oi = __shfl_xor_sync(0xFFFFFFFFu, bk, o);
            if (ov < bv || (ov == bv && oi < bk)) { bv = ov; bk = oi; }
        }
        if (lane == 0) { rv[wid] = bv; rix[wid] = bk; }
        __syncthreads();
        if (tid == 0) {
            float v = rv[0]; int ix = rix[0];
            #pragma unroll
            for (int w = 1; w < 8; w++)
                if (rv[w] < v || (rv[w] == v && rix[w] < ix)) { v = rv[w]; ix = rix[w]; }
            g_codes[r] = ix;
            out[CODES_OFF + r] = (float)ix;
        }
        __syncthreads();
    }
}

// ---------------- gather z_q + loss ----------------
__global__ __launch_bounds__(256, 1)
void vq_gather(const float* __restrict__ z, const float* __restrict__ emb,
               float* __restrict__ out) {
    __shared__ float red[8];
    const int tid = threadIdx.x, wid = tid >> 5, lane = tid & 31;
    const int n0 = blockIdx.x * MT;
    const int b = n0 >> 10, hw0 = n0 & (HW - 1);
    const int nl = tid & 127, half = tid >> 7;
    const int code = __ldg(g_codes + n0 + nl);
    const float4* er = reinterpret_cast<const float4*>(emb + (size_t)code * DIM);
    float* zq = out + (size_t)b * DIM * HW + hw0 + nl;
    const float* zr = z + (size_t)b * DIM * HW + hw0 + nl;
    float lsum = 0.f;
    #pragma unroll 4
    for (int d4 = half; d4 < 64; d4 += 2) {
        float4 e = __ldg(er + d4);
        const int o0 = (d4 * 4) * HW;
        float z0 = zr[o0], z1 = zr[o0 + HW], z2 = zr[o0 + 2 * HW], z3 = zr[o0 + 3 * HW];
        zq[o0] = e.x; zq[o0 + HW] = e.y; zq[o0 + 2 * HW] = e.z; zq[o0 + 3 * HW] = e.w;
        float d0 = e.x - z0, d1 = e.y - z1, d2 = e.z - z2, d3 = e.w - z3;
        lsum = fmaf(d0, d0, lsum); lsum = fmaf(d1, d1, lsum);
        lsum = fmaf(d2, d2, lsum); lsum = fmaf(d3, d3, lsum);
    }
    #pragma unroll
    for (int o = 16; o; o >>= 1) lsum += __shfl_xor_sync(0xFFFFFFFFu, lsum, o);
    if (lane == 0) red[wid] = lsum;
    __syncthreads();
    if (tid == 0) {
        float s = 0.f;
        #pragma unroll
        for (int w = 0; w < 8; w++) s += red[w];
        g_partials[blockIdx.x] = s;
    }
}

// ---------------- finalize ----------------
__global__ void vq_fin(float* __restrict__ out) {
    if (threadIdx.x == 0 && blockIdx.x == 0) {
        float s = 0.f;
        for (int i = 0; i < GBLOCKS; i++) s += g_partials[i];
        out[LOSS_OFF] = 1.25f * s / (float)ZQ_ELEMS;
    }
}

extern "C" void kernel_launch(void* const* d_in, const int* in_sizes, int n_in,
                              void* d_out, int out_size) {
    const float* z   = (const float*)d_in[0];
    const float* emb = (const float*)d_in[1];
    if (n_in >= 2 && in_sizes[0] == KCODES * DIM) { const float* t = z; z = emb; emb = t; }
    float* out = (float*)d_out;

    cudaFuncSetAttribute(vq_gemm, cudaFuncAttributeMaxDynamicSharedMemorySize, SMEM_BYTES);
    vq_prep_e<<<(KCODES * 32 + 255) / 256, 256>>>(emb);
    vq_gemm<<<GBLOCKS, 256, SMEM_BYTES>>>(z, out);
    vq_refineA<<<128, 256>>>(z, emb, out);
    vq_refineB<<<256, 256>>>(z, emb, out);
    vq_gather<<<GBLOCKS, 256>>>(z, emb, out);
    vq_fin<<<1, 32>>>(out);
}